// round 2
// baseline (speedup 1.0000x reference)
#include <cuda_runtime.h>
#include <cuda_bf16.h>
#include <math.h>

#define N_RAYS 262144
#define HASHMAP_SIZE 524288
#define HMASK 0x7FFFFu
#define DIM 256
#define N_MID 6
#define PRIME1 2654435761u

// ---------------- static scratch (no allocations allowed) ----------------
__device__ float g_emb[(size_t)N_RAYS * 16];
__device__ float g_h0[(size_t)N_RAYS * DIM];
__device__ float g_h1[(size_t)N_RAYS * DIM];

// ---------------- hash encode ----------------
__global__ __launch_bounds__(256) void encode_kernel(
    const float* __restrict__ x,
    const float* __restrict__ t1,
    const float* __restrict__ t2,
    int4 res)
{
    int n = blockIdx.x * blockDim.x + threadIdx.x;
    if (n >= N_RAYS) return;
    float4 xv = ((const float4*)x)[n];
    int rs[4] = {res.x, res.y, res.z, res.w};
    float out[16];

#pragma unroll
    for (int e = 0; e < 2; e++) {
        float px = e ? xv.z : xv.x;
        float py = e ? xv.w : xv.y;
        const float* tab = e ? t2 : t1;
#pragma unroll
        for (int l = 0; l < 4; l++) {
            float r = (float)rs[l];
            float xf0 = px * r;
            float xf1 = py * r;
            float xi0 = floorf(xf0);
            float xi1 = floorf(xf1);
            float fx = xf0 - xi0;
            float fy = xf1 - xi1;
            unsigned u0 = (unsigned)xi0;
            unsigned u1 = (unsigned)xi1;
            const float2* T = (const float2*)(tab + (size_t)l * HASHMAP_SIZE * 2);
            unsigned a0 = u0;
            unsigned a1 = u0 + 1u;
            unsigned b0 = u1 * PRIME1;
            unsigned b1 = (u1 + 1u) * PRIME1;
            float2 v00 = T[(a0 ^ b0) & HMASK];
            float2 v01 = T[(a0 ^ b1) & HMASK];
            float2 v10 = T[(a1 ^ b0) & HMASK];
            float2 v11 = T[(a1 ^ b1) & HMASK];
            float w00 = (1.0f - fx) * (1.0f - fy);
            float w01 = (1.0f - fx) * fy;
            float w10 = fx * (1.0f - fy);
            float w11 = fx * fy;
            out[e * 8 + l * 2 + 0] = w00 * v00.x + w01 * v01.x + w10 * v10.x + w11 * v11.x;
            out[e * 8 + l * 2 + 1] = w00 * v00.y + w01 * v01.y + w10 * v10.y + w11 * v11.y;
        }
    }
    float4* eo = (float4*)(g_emb + (size_t)n * 16);
#pragma unroll
    for (int i = 0; i < 4; i++)
        eo[i] = make_float4(out[i * 4], out[i * 4 + 1], out[i * 4 + 2], out[i * 4 + 3]);
}

// ---------------- input layer: [N,16] @ [16,256] + b ----------------
__global__ __launch_bounds__(256) void lin_kernel(
    const float* __restrict__ Win,
    const float* __restrict__ bin)
{
    __shared__ float Es[64][16];
    int tid = threadIdx.x;
    size_t r0 = (size_t)blockIdx.x * 64;

    // load 64x16 emb tile: 256 threads x 1 float4
    {
        int row = tid >> 2;
        int col = (tid & 3) * 4;
        float4 v = *(const float4*)(g_emb + (r0 + row) * 16 + col);
        *(float4*)&Es[row][col] = v;
    }
    // each thread owns one output column
    float wc[16];
#pragma unroll
    for (int k = 0; k < 16; k++) wc[k] = Win[k * 256 + tid];
    float bc = bin[tid];
    __syncthreads();

#pragma unroll 4
    for (int r = 0; r < 64; r++) {
        float s = bc;
#pragma unroll
        for (int k = 0; k < 16; k++) s += Es[r][k] * wc[k];
        g_h0[(r0 + r) * DIM + tid] = s;
    }
}

// ---------------- mid layer: C = relu(A) @ W + b  (A,W,C: [*,256]) ----------------
#define BM 128
#define BN 128
#define BK 8
#define TM 8
#define TN 8

__global__ __launch_bounds__(256) void mid_kernel(
    const float* __restrict__ A,
    const float* __restrict__ W,
    const float* __restrict__ bias,
    float* __restrict__ C)
{
    __shared__ float As[BK][BM];
    __shared__ float Bs[BK][BN];

    int tid = threadIdx.x;
    size_t bm = (size_t)blockIdx.x * BM;
    int bn = blockIdx.y * BN;

    int arow = tid >> 1;            // 0..127
    int acol = (tid & 1) * 4;       // 0 or 4
    int brow = tid >> 5;            // 0..7
    int bcol = (tid & 31) * 4;      // 0..124

    int tx = tid & 15;              // col group
    int ty = tid >> 4;              // row group

    float acc[TM][TN];
#pragma unroll
    for (int i = 0; i < TM; i++)
#pragma unroll
        for (int j = 0; j < TN; j++) acc[i][j] = 0.0f;

    const float* Aptr = A + (bm + arow) * DIM;

    for (int k0 = 0; k0 < DIM; k0 += BK) {
        float4 av = *(const float4*)(Aptr + k0 + acol);
        av.x = fmaxf(av.x, 0.0f);
        av.y = fmaxf(av.y, 0.0f);
        av.z = fmaxf(av.z, 0.0f);
        av.w = fmaxf(av.w, 0.0f);
        As[acol + 0][arow] = av.x;
        As[acol + 1][arow] = av.y;
        As[acol + 2][arow] = av.z;
        As[acol + 3][arow] = av.w;

        float4 bv = *(const float4*)(W + (size_t)(k0 + brow) * DIM + bn + bcol);
        *(float4*)&Bs[brow][bcol] = bv;

        __syncthreads();

#pragma unroll
        for (int k = 0; k < BK; k++) {
            float4 a0 = *(const float4*)&As[k][ty * TM];
            float4 a1 = *(const float4*)&As[k][ty * TM + 4];
            float4 b0 = *(const float4*)&Bs[k][tx * TN];
            float4 b1 = *(const float4*)&Bs[k][tx * TN + 4];
            float a[TM] = {a0.x, a0.y, a0.z, a0.w, a1.x, a1.y, a1.z, a1.w};
            float b[TN] = {b0.x, b0.y, b0.z, b0.w, b1.x, b1.y, b1.z, b1.w};
#pragma unroll
            for (int i = 0; i < TM; i++)
#pragma unroll
                for (int j = 0; j < TN; j++)
                    acc[i][j] = fmaf(a[i], b[j], acc[i][j]);
        }
        __syncthreads();
    }

    // epilogue: add bias, store
    float4 bb0 = *(const float4*)(bias + bn + tx * TN);
    float4 bb1 = *(const float4*)(bias + bn + tx * TN + 4);
    float bj[TN] = {bb0.x, bb0.y, bb0.z, bb0.w, bb1.x, bb1.y, bb1.z, bb1.w};
#pragma unroll
    for (int i = 0; i < TM; i++) {
        float4 o0 = make_float4(acc[i][0] + bj[0], acc[i][1] + bj[1],
                                acc[i][2] + bj[2], acc[i][3] + bj[3]);
        float4 o1 = make_float4(acc[i][4] + bj[4], acc[i][5] + bj[5],
                                acc[i][6] + bj[6], acc[i][7] + bj[7]);
        float* cp = C + (bm + ty * TM + i) * DIM + bn + tx * TN;
        *(float4*)cp = o0;
        *(float4*)(cp + 4) = o1;
    }
}

// ---------------- output head: out[n] = relu(h[n]) . Wout + bout ----------------
__global__ __launch_bounds__(256) void out_kernel(
    const float* __restrict__ H,
    const float* __restrict__ Wout,
    const float* __restrict__ bout,
    float* __restrict__ out)
{
    __shared__ float ws[256];
    int tid = threadIdx.x;
    ws[tid] = Wout[tid];
    __syncthreads();
    int warp = tid >> 5;
    int lane = tid & 31;
    size_t n = (size_t)blockIdx.x * 8 + warp;
    const float* h = H + n * DIM;
    float s = 0.0f;
#pragma unroll
    for (int i = 0; i < 8; i++) {
        int c = lane + i * 32;
        s += fmaxf(h[c], 0.0f) * ws[c];
    }
#pragma unroll
    for (int off = 16; off > 0; off >>= 1)
        s += __shfl_xor_sync(0xFFFFFFFFu, s, off);
    if (lane == 0) out[n] = s + bout[0];
}

// ---------------- launch ----------------
extern "C" void kernel_launch(void* const* d_in, const int* in_sizes, int n_in,
                              void* d_out, int out_size)
{
    const float* x      = (const float*)d_in[0];
    const float* table1 = (const float*)d_in[1];
    const float* table2 = (const float*)d_in[2];
    const float* W_in   = (const float*)d_in[3];
    const float* b_in   = (const float*)d_in[4];
    const float* W_mid  = (const float*)d_in[5];
    const float* b_mid  = (const float*)d_in[6];
    const float* W_out  = (const float*)d_in[7];
    const float* b_out  = (const float*)d_in[8];
    float* out = (float*)d_out;

    // Replicate Python's RESOLUTIONS computation exactly (same libm on host).
    double bgrow = exp((log(512.0) - log(16.0)) / 3.0);
    int r[4];
    for (int l = 0; l < 4; l++) r[l] = (int)floor(16.0 * pow(bgrow, (double)l));
    int4 res = make_int4(r[0], r[1], r[2], r[3]);

    float* h0;
    float* h1;
    cudaGetSymbolAddress((void**)&h0, g_h0);
    cudaGetSymbolAddress((void**)&h1, g_h1);

    encode_kernel<<<N_RAYS / 256, 256>>>(x, table1, table2, res);
    lin_kernel<<<N_RAYS / 64, 256>>>(W_in, b_in);

    dim3 grid(N_RAYS / BM, DIM / BN);
    const float* cur = h0;
    float* nxt = h1;
    for (int i = 0; i < N_MID; i++) {
        mid_kernel<<<grid, 256>>>(cur, W_mid + (size_t)i * DIM * DIM,
                                  b_mid + (size_t)i * DIM, nxt);
        const float* t = cur;
        cur = nxt;
        nxt = (float*)t;
    }
    out_kernel<<<N_RAYS / 8, 256>>>(cur, W_out, b_out, out);
}

// round 3
// speedup vs baseline: 1.0030x; 1.0030x over previous
#include <cuda_runtime.h>
#include <cuda_bf16.h>
#include <math.h>

#define N_RAYS 262144
#define HASHMAP_SIZE 524288
#define HMASK 0x7FFFFu
#define DIM 256
#define N_MID 6
#define PRIME1 2654435761u

// ---------------- static scratch (no allocations allowed) ----------------
__device__ float g_emb[(size_t)N_RAYS * 16];
__device__ float g_h0[(size_t)N_RAYS * DIM];
__device__ float g_h1[(size_t)N_RAYS * DIM];

// ---------------- hash encode ----------------
__global__ __launch_bounds__(256) void encode_kernel(
    const float* __restrict__ x,
    const float* __restrict__ t1,
    const float* __restrict__ t2,
    int4 res)
{
    int n = blockIdx.x * blockDim.x + threadIdx.x;
    if (n >= N_RAYS) return;
    float4 xv = ((const float4*)x)[n];
    int rs[4] = {res.x, res.y, res.z, res.w};
    float out[16];

#pragma unroll
    for (int e = 0; e < 2; e++) {
        float px = e ? xv.z : xv.x;
        float py = e ? xv.w : xv.y;
        const float* tab = e ? t2 : t1;
#pragma unroll
        for (int l = 0; l < 4; l++) {
            float r = (float)rs[l];
            float xf0 = px * r;
            float xf1 = py * r;
            float xi0 = floorf(xf0);
            float xi1 = floorf(xf1);
            float fx = xf0 - xi0;
            float fy = xf1 - xi1;
            unsigned u0 = (unsigned)xi0;
            unsigned u1 = (unsigned)xi1;
            const float2* T = (const float2*)(tab + (size_t)l * HASHMAP_SIZE * 2);
            unsigned a0 = u0;
            unsigned a1 = u0 + 1u;
            unsigned b0 = u1 * PRIME1;
            unsigned b1 = (u1 + 1u) * PRIME1;
            float2 v00 = T[(a0 ^ b0) & HMASK];
            float2 v01 = T[(a0 ^ b1) & HMASK];
            float2 v10 = T[(a1 ^ b0) & HMASK];
            float2 v11 = T[(a1 ^ b1) & HMASK];
            float w00 = (1.0f - fx) * (1.0f - fy);
            float w01 = (1.0f - fx) * fy;
            float w10 = fx * (1.0f - fy);
            float w11 = fx * fy;
            out[e * 8 + l * 2 + 0] = w00 * v00.x + w01 * v01.x + w10 * v10.x + w11 * v11.x;
            out[e * 8 + l * 2 + 1] = w00 * v00.y + w01 * v01.y + w10 * v10.y + w11 * v11.y;
        }
    }
    float4* eo = (float4*)(g_emb + (size_t)n * 16);
#pragma unroll
    for (int i = 0; i < 4; i++)
        eo[i] = make_float4(out[i * 4], out[i * 4 + 1], out[i * 4 + 2], out[i * 4 + 3]);
}

// ---------------- input layer: [N,16] @ [16,256] + b ----------------
__global__ __launch_bounds__(256) void lin_kernel(
    const float* __restrict__ Win,
    const float* __restrict__ bin)
{
    __shared__ float Es[64][16];
    int tid = threadIdx.x;
    size_t r0 = (size_t)blockIdx.x * 64;

    // load 64x16 emb tile: 256 threads x 1 float4
    {
        int row = tid >> 2;
        int col = (tid & 3) * 4;
        float4 v = *(const float4*)(g_emb + (r0 + row) * 16 + col);
        *(float4*)&Es[row][col] = v;
    }
    // each thread owns one output column
    float wc[16];
#pragma unroll
    for (int k = 0; k < 16; k++) wc[k] = Win[k * 256 + tid];
    float bc = bin[tid];
    __syncthreads();

#pragma unroll 4
    for (int r = 0; r < 64; r++) {
        float s = bc;
#pragma unroll
        for (int k = 0; k < 16; k++) s += Es[r][k] * wc[k];
        g_h0[(r0 + r) * DIM + tid] = s;
    }
}

// ---------------- mid layer: C = relu(A) @ W + b  (A,W,C: [*,256]) ----------------
#define BM 128
#define BN 128
#define BK 8
#define TM 8
#define TN 8

__global__ __launch_bounds__(256) void mid_kernel(
    const float* __restrict__ A,
    const float* __restrict__ W,
    const float* __restrict__ bias,
    float* __restrict__ C)
{
    __shared__ float As[BK][BM];
    __shared__ float Bs[BK][BN];

    int tid = threadIdx.x;
    size_t bm = (size_t)blockIdx.x * BM;
    int bn = blockIdx.y * BN;

    int arow = tid >> 1;            // 0..127
    int acol = (tid & 1) * 4;       // 0 or 4
    int brow = tid >> 5;            // 0..7
    int bcol = (tid & 31) * 4;      // 0..124

    int tx = tid & 15;              // col group
    int ty = tid >> 4;              // row group

    float acc[TM][TN];
#pragma unroll
    for (int i = 0; i < TM; i++)
#pragma unroll
        for (int j = 0; j < TN; j++) acc[i][j] = 0.0f;

    const float* Aptr = A + (bm + arow) * DIM;

    for (int k0 = 0; k0 < DIM; k0 += BK) {
        float4 av = *(const float4*)(Aptr + k0 + acol);
        av.x = fmaxf(av.x, 0.0f);
        av.y = fmaxf(av.y, 0.0f);
        av.z = fmaxf(av.z, 0.0f);
        av.w = fmaxf(av.w, 0.0f);
        As[acol + 0][arow] = av.x;
        As[acol + 1][arow] = av.y;
        As[acol + 2][arow] = av.z;
        As[acol + 3][arow] = av.w;

        float4 bv = *(const float4*)(W + (size_t)(k0 + brow) * DIM + bn + bcol);
        *(float4*)&Bs[brow][bcol] = bv;

        __syncthreads();

#pragma unroll
        for (int k = 0; k < BK; k++) {
            float4 a0 = *(const float4*)&As[k][ty * TM];
            float4 a1 = *(const float4*)&As[k][ty * TM + 4];
            float4 b0 = *(const float4*)&Bs[k][tx * TN];
            float4 b1 = *(const float4*)&Bs[k][tx * TN + 4];
            float a[TM] = {a0.x, a0.y, a0.z, a0.w, a1.x, a1.y, a1.z, a1.w};
            float b[TN] = {b0.x, b0.y, b0.z, b0.w, b1.x, b1.y, b1.z, b1.w};
#pragma unroll
            for (int i = 0; i < TM; i++)
#pragma unroll
                for (int j = 0; j < TN; j++)
                    acc[i][j] = fmaf(a[i], b[j], acc[i][j]);
        }
        __syncthreads();
    }

    // epilogue: add bias, store
    float4 bb0 = *(const float4*)(bias + bn + tx * TN);
    float4 bb1 = *(const float4*)(bias + bn + tx * TN + 4);
    float bj[TN] = {bb0.x, bb0.y, bb0.z, bb0.w, bb1.x, bb1.y, bb1.z, bb1.w};
#pragma unroll
    for (int i = 0; i < TM; i++) {
        float4 o0 = make_float4(acc[i][0] + bj[0], acc[i][1] + bj[1],
                                acc[i][2] + bj[2], acc[i][3] + bj[3]);
        float4 o1 = make_float4(acc[i][4] + bj[4], acc[i][5] + bj[5],
                                acc[i][6] + bj[6], acc[i][7] + bj[7]);
        float* cp = C + (bm + ty * TM + i) * DIM + bn + tx * TN;
        *(float4*)cp = o0;
        *(float4*)(cp + 4) = o1;
    }
}

// ---------------- output head: out[n] = relu(h[n]) . Wout + bout ----------------
__global__ __launch_bounds__(256) void out_kernel(
    const float* __restrict__ H,
    const float* __restrict__ Wout,
    const float* __restrict__ bout,
    float* __restrict__ out)
{
    __shared__ float ws[256];
    int tid = threadIdx.x;
    ws[tid] = Wout[tid];
    __syncthreads();
    int warp = tid >> 5;
    int lane = tid & 31;
    size_t n = (size_t)blockIdx.x * 8 + warp;
    const float* h = H + n * DIM;
    float s = 0.0f;
#pragma unroll
    for (int i = 0; i < 8; i++) {
        int c = lane + i * 32;
        s += fmaxf(h[c], 0.0f) * ws[c];
    }
#pragma unroll
    for (int off = 16; off > 0; off >>= 1)
        s += __shfl_xor_sync(0xFFFFFFFFu, s, off);
    if (lane == 0) out[n] = s + bout[0];
}

// ---------------- launch ----------------
extern "C" void kernel_launch(void* const* d_in, const int* in_sizes, int n_in,
                              void* d_out, int out_size)
{
    const float* x      = (const float*)d_in[0];
    const float* table1 = (const float*)d_in[1];
    const float* table2 = (const float*)d_in[2];
    const float* W_in   = (const float*)d_in[3];
    const float* b_in   = (const float*)d_in[4];
    const float* W_mid  = (const float*)d_in[5];
    const float* b_mid  = (const float*)d_in[6];
    const float* W_out  = (const float*)d_in[7];
    const float* b_out  = (const float*)d_in[8];
    float* out = (float*)d_out;

    // Replicate Python's RESOLUTIONS computation exactly (same libm on host).
    double bgrow = exp((log(512.0) - log(16.0)) / 3.0);
    int r[4];
    for (int l = 0; l < 4; l++) r[l] = (int)floor(16.0 * pow(bgrow, (double)l));
    int4 res = make_int4(r[0], r[1], r[2], r[3]);

    float* h0;
    float* h1;
    cudaGetSymbolAddress((void**)&h0, g_h0);
    cudaGetSymbolAddress((void**)&h1, g_h1);

    encode_kernel<<<N_RAYS / 256, 256>>>(x, table1, table2, res);
    lin_kernel<<<N_RAYS / 64, 256>>>(W_in, b_in);

    dim3 grid(N_RAYS / BM, DIM / BN);
    const float* cur = h0;
    float* nxt = h1;
    for (int i = 0; i < N_MID; i++) {
        mid_kernel<<<grid, 256>>>(cur, W_mid + (size_t)i * DIM * DIM,
                                  b_mid + (size_t)i * DIM, nxt);
        const float* t = cur;
        cur = nxt;
        nxt = (float*)t;
    }
    out_kernel<<<N_RAYS / 8, 256>>>(cur, W_out, b_out, out);
}

// round 7
// speedup vs baseline: 2.2574x; 2.2507x over previous
#include <cuda_runtime.h>
#include <cuda_bf16.h>
#include <cstdint>
#include <math.h>

#define N_RAYS 262144
#define HASHMAP_SIZE 524288
#define HMASK 0x7FFFFu
#define DIM 256
#define N_MID 6
#define PRIME1 2654435761u

#define TILE_M 128
// A-activation SMEM buffer: 128 rows x 264 bf16 (stride picked for conflict-free ldmatrix)
#define SA_B 528                      // row stride bytes
#define ABUF_B (TILE_M * SA_B)        // 67584
#define AHI_OFF 0
#define ALO_OFF ABUF_B
#define BIAS_OFF (2 * ABUF_B)         // 135168, 7*256 floats
#define WOUT_OFF (BIAS_OFF + 7 * 256 * 4)   // 142336
#define PART_OFF (WOUT_OFF + 1024)          // 143360
#define SMEM_TOTAL (PART_OFF + 512)         // 143872

// fragment-packed weights: uint2 = {b0,b1} regs of mma.m16n8k16 B operand
// mid: [l(6)][kt(16)][nt(32)][lane(32)] ; in: [nt(32)][lane(32)]
#define PKM_PER_LAYER (16 * 32 * 32)        // 16384
__device__ uint2 g_pkm_hi[N_MID * PKM_PER_LAYER];
__device__ uint2 g_pkm_lo[N_MID * PKM_PER_LAYER];
__device__ uint2 g_pki_hi[32 * 32];
__device__ uint2 g_pki_lo[32 * 32];

__device__ __forceinline__ uint32_t smem_u32(const void* p) {
    uint32_t a;
    asm("{ .reg .u64 t; cvta.to.shared.u64 t, %1; cvt.u32.u64 %0, t; }" : "=r"(a) : "l"(p));
    return a;
}
__device__ __forceinline__ uint32_t pack_bf2(__nv_bfloat16 a, __nv_bfloat16 b) {
    return (uint32_t)__bfloat16_as_ushort(a) | ((uint32_t)__bfloat16_as_ushort(b) << 16);
}
__device__ __forceinline__ void split_bf(float v, __nv_bfloat16& h, __nv_bfloat16& l) {
    h = __float2bfloat16(v);
    l = __float2bfloat16(v - __bfloat162float(h));
}

#define MMA(d, a, b0v, b1v) \
    asm volatile("mma.sync.aligned.m16n8k16.row.col.f32.bf16.bf16.f32 " \
        "{%0,%1,%2,%3},{%4,%5,%6,%7},{%8,%9},{%0,%1,%2,%3};" \
        : "+f"((d)[0]), "+f"((d)[1]), "+f"((d)[2]), "+f"((d)[3]) \
        : "r"((a)[0]), "r"((a)[1]), "r"((a)[2]), "r"((a)[3]), "r"(b0v), "r"(b1v))

#define LDSM4(r, addr) \
    asm volatile("ldmatrix.sync.aligned.m8n8.x4.shared.b16 {%0,%1,%2,%3}, [%4];" \
        : "=r"((r)[0]), "=r"((r)[1]), "=r"((r)[2]), "=r"((r)[3]) : "r"(addr))

// ---------------- weight prep: fp32 -> per-thread MMA fragments (bf16 hi/lo) ----------------
// element (l,kt,nt,t): b0 covers k = kt*16 + (t&3)*2 {,+1}; b1 = +8; n = nt*8 + (t>>2)
#define PREP_MID (N_MID * PKM_PER_LAYER)    // 98304
#define PREP_TOT (PREP_MID + 1024)
__global__ __launch_bounds__(256) void prep_kernel(
    const float* __restrict__ Wmid, const float* __restrict__ Win)
{
    int idx = blockIdx.x * 256 + threadIdx.x;
    if (idx >= PREP_TOT) return;
    const float* W;
    int t, nt, k0base, out_idx;
    bool is_in = idx >= PREP_MID;
    if (is_in) {
        int i2 = idx - PREP_MID;
        t = i2 & 31; nt = (i2 >> 5) & 31;
        k0base = 0; W = Win; out_idx = i2;
    } else {
        t = idx & 31; nt = (idx >> 5) & 31;
        int kt = (idx >> 10) & 15; int l = idx >> 14;
        k0base = kt * 16; W = Wmid + (size_t)l * DIM * DIM; out_idx = idx;
    }
    int n = nt * 8 + (t >> 2);
    int k0 = k0base + (t & 3) * 2;
    float w00 = W[(size_t)k0 * DIM + n];
    float w01 = W[(size_t)(k0 + 1) * DIM + n];
    float w10 = W[(size_t)(k0 + 8) * DIM + n];
    float w11 = W[(size_t)(k0 + 9) * DIM + n];
    __nv_bfloat16 h, l2;
    uint2 hi, lo;
    __nv_bfloat16 h0, l0, h1, l1;
    split_bf(w00, h0, l0); split_bf(w01, h1, l1);
    hi.x = pack_bf2(h0, h1); lo.x = pack_bf2(l0, l1);
    split_bf(w10, h0, l0); split_bf(w11, h1, l1);
    hi.y = pack_bf2(h0, h1); lo.y = pack_bf2(l0, l1);
    (void)h; (void)l2;
    if (is_in) { g_pki_hi[out_idx] = hi; g_pki_lo[out_idx] = lo; }
    else       { g_pkm_hi[out_idx] = hi; g_pkm_lo[out_idx] = lo; }
}

// ---------------- one K=16 step: 3-term split MMA over 8 m-tiles x 4 n-tiles ----------------
__device__ __forceinline__ void do_kt(
    uint32_t kt_boff, const uint2* __restrict__ pp_hi, const uint2* __restrict__ pp_lo,
    uint32_t smAhi, uint32_t a_lane_off, float (&acc)[8][4][4])
{
    uint2 bh[4], bl[4];
#pragma unroll
    for (int j = 0; j < 4; j++) { bh[j] = pp_hi[j * 32]; bl[j] = pp_lo[j * 32]; }
#pragma unroll
    for (int mb = 0; mb < 2; mb++) {
        uint32_t ah[4][4], al[4][4];
#pragma unroll
        for (int mm = 0; mm < 4; mm++) {
            uint32_t addr = smAhi + a_lane_off + (uint32_t)(mb * 4 + mm) * (16 * SA_B) + kt_boff;
            LDSM4(ah[mm], addr);
            LDSM4(al[mm], addr + ABUF_B);
        }
#pragma unroll
        for (int mm = 0; mm < 4; mm++)
#pragma unroll
            for (int j = 0; j < 4; j++) MMA(acc[mb * 4 + mm][j], ah[mm], bh[j].x, bh[j].y);
#pragma unroll
        for (int mm = 0; mm < 4; mm++)
#pragma unroll
            for (int j = 0; j < 4; j++) MMA(acc[mb * 4 + mm][j], ah[mm], bl[j].x, bl[j].y);
#pragma unroll
        for (int mm = 0; mm < 4; mm++)
#pragma unroll
            for (int j = 0; j < 4; j++) MMA(acc[mb * 4 + mm][j], al[mm], bh[j].x, bh[j].y);
    }
}

// ---------------- fused model ----------------
__global__ __launch_bounds__(256, 1) void fused_kernel(
    const float* __restrict__ x,
    const float* __restrict__ t1,
    const float* __restrict__ t2,
    const float* __restrict__ b_in,
    const float* __restrict__ b_mid,
    const float* __restrict__ W_out,
    const float* __restrict__ b_out,
    float* __restrict__ out,
    int4 res)
{
    extern __shared__ char smem[];
    float* sbias = (float*)(smem + BIAS_OFF);
    float* swout = (float*)(smem + WOUT_OFF);
    float* spart = (float*)(smem + PART_OFF);
    int tid = threadIdx.x;
    int w = tid >> 5;
    int t = tid & 31;

    // prologue: biases, wout, partial init
    sbias[tid] = b_in[tid];
#pragma unroll
    for (int l = 0; l < N_MID; l++) sbias[(l + 1) * 256 + tid] = b_mid[(size_t)l * 256 + tid];
    swout[tid] = W_out[tid];
    if (tid < 128) spart[tid] = 0.0f;

    // encode: threads 0-127 -> row tid of A buffers (cols 0-15)
    if (tid < 128) {
        int ray = blockIdx.x * TILE_M + tid;
        float4 xv = ((const float4*)x)[ray];
        int rs[4] = {res.x, res.y, res.z, res.w};
        float e[16];
#pragma unroll
        for (int enc = 0; enc < 2; enc++) {
            float px = enc ? xv.z : xv.x;
            float py = enc ? xv.w : xv.y;
            const float* tab = enc ? t2 : t1;
#pragma unroll
            for (int l = 0; l < 4; l++) {
                float r = (float)rs[l];
                float xf0 = px * r, xf1 = py * r;
                float xi0 = floorf(xf0), xi1 = floorf(xf1);
                float fx = xf0 - xi0, fy = xf1 - xi1;
                unsigned u0 = (unsigned)xi0, u1 = (unsigned)xi1;
                const float2* T = (const float2*)(tab + (size_t)l * HASHMAP_SIZE * 2);
                unsigned b0 = u1 * PRIME1, b1 = (u1 + 1u) * PRIME1;
                float2 v00 = T[(u0 ^ b0) & HMASK];
                float2 v01 = T[(u0 ^ b1) & HMASK];
                float2 v10 = T[((u0 + 1u) ^ b0) & HMASK];
                float2 v11 = T[((u0 + 1u) ^ b1) & HMASK];
                float w00 = (1.f - fx) * (1.f - fy), w01 = (1.f - fx) * fy;
                float w10 = fx * (1.f - fy), w11 = fx * fy;
                e[enc * 8 + l * 2 + 0] = w00 * v00.x + w01 * v01.x + w10 * v10.x + w11 * v11.x;
                e[enc * 8 + l * 2 + 1] = w00 * v00.y + w01 * v01.y + w10 * v10.y + w11 * v11.y;
            }
        }
        uint32_t* rh = (uint32_t*)(smem + AHI_OFF + tid * SA_B);
        uint32_t* rl = (uint32_t*)(smem + ALO_OFF + tid * SA_B);
#pragma unroll
        for (int j = 0; j < 8; j++) {
            __nv_bfloat16 h0, l0, h1, l1;
            split_bf(e[2 * j], h0, l0);
            split_bf(e[2 * j + 1], h1, l1);
            rh[j] = pack_bf2(h0, h1);
            rl[j] = pack_bf2(l0, l1);
        }
    }
    __syncthreads();

    uint32_t smAhi = smem_u32(smem);
    uint32_t a_lane_off = (uint32_t)(t & 15) * SA_B + (uint32_t)(t >> 4) * 16;

    float acc[8][4][4];

    for (int g = 0; g < 7; g++) {
#pragma unroll
        for (int m = 0; m < 8; m++)
#pragma unroll
            for (int j = 0; j < 4; j++)
#pragma unroll
                for (int q = 0; q < 4; q++) acc[m][j][q] = 0.0f;

        if (g == 0) {
            do_kt(0, g_pki_hi + w * 128 + t, g_pki_lo + w * 128 + t, smAhi, a_lane_off, acc);
        } else {
            const uint2* bh = g_pkm_hi + (size_t)(g - 1) * PKM_PER_LAYER + w * 128 + t;
            const uint2* bl = g_pkm_lo + (size_t)(g - 1) * PKM_PER_LAYER + w * 128 + t;
#pragma unroll 1
            for (int kt = 0; kt < 16; kt++)
                do_kt((uint32_t)kt * 32, bh + kt * 1024, bl + kt * 1024, smAhi, a_lane_off, acc);
        }
        __syncthreads();   // all warps done reading A

        if (g < 6) {
            const float* bs = sbias + g * 256;
#pragma unroll
            for (int m = 0; m < 8; m++) {
#pragma unroll
                for (int j = 0; j < 4; j++) {
                    int r0 = m * 16 + (t >> 2);
                    int c0 = w * 32 + j * 8 + (t & 3) * 2;
                    float v0 = fmaxf(acc[m][j][0] + bs[c0], 0.0f);
                    float v1 = fmaxf(acc[m][j][1] + bs[c0 + 1], 0.0f);
                    float v2 = fmaxf(acc[m][j][2] + bs[c0], 0.0f);
                    float v3 = fmaxf(acc[m][j][3] + bs[c0 + 1], 0.0f);
                    __nv_bfloat16 h0, l0, h1, l1;
                    split_bf(v0, h0, l0); split_bf(v1, h1, l1);
                    *(uint32_t*)(smem + AHI_OFF + r0 * SA_B + c0 * 2) = pack_bf2(h0, h1);
                    *(uint32_t*)(smem + ALO_OFF + r0 * SA_B + c0 * 2) = pack_bf2(l0, l1);
                    split_bf(v2, h0, l0); split_bf(v3, h1, l1);
                    *(uint32_t*)(smem + AHI_OFF + (r0 + 8) * SA_B + c0 * 2) = pack_bf2(h0, h1);
                    *(uint32_t*)(smem + ALO_OFF + (r0 + 8) * SA_B + c0 * 2) = pack_bf2(l0, l1);
                }
            }
            __syncthreads();
        } else {
            // output head: relu(D + b_mid[5]) . W_out + b_out
            const float* bs = sbias + 6 * 256;
#pragma unroll
            for (int m = 0; m < 8; m++) {
                float s0 = 0.0f, s1 = 0.0f;
#pragma unroll
                for (int j = 0; j < 4; j++) {
                    int c0 = w * 32 + j * 8 + (t & 3) * 2;
                    s0 += fmaxf(acc[m][j][0] + bs[c0], 0.0f) * swout[c0]
                        + fmaxf(acc[m][j][1] + bs[c0 + 1], 0.0f) * swout[c0 + 1];
                    s1 += fmaxf(acc[m][j][2] + bs[c0], 0.0f) * swout[c0]
                        + fmaxf(acc[m][j][3] + bs[c0 + 1], 0.0f) * swout[c0 + 1];
                }
                s0 += __shfl_xor_sync(0xFFFFFFFFu, s0, 1);
                s0 += __shfl_xor_sync(0xFFFFFFFFu, s0, 2);
                s1 += __shfl_xor_sync(0xFFFFFFFFu, s1, 1);
                s1 += __shfl_xor_sync(0xFFFFFFFFu, s1, 2);
                if ((t & 3) == 0) {
                    atomicAdd(&spart[m * 16 + (t >> 2)], s0);
                    atomicAdd(&spart[m * 16 + (t >> 2) + 8], s1);
                }
            }
            __syncthreads();
            if (tid < 128)
                out[blockIdx.x * TILE_M + tid] = spart[tid] + b_out[0];
        }
    }
}

// ---------------- launch ----------------
extern "C" void kernel_launch(void* const* d_in, const int* in_sizes, int n_in,
                              void* d_out, int out_size)
{
    const float* x      = (const float*)d_in[0];
    const float* table1 = (const float*)d_in[1];
    const float* table2 = (const float*)d_in[2];
    const float* W_in   = (const float*)d_in[3];
    const float* b_in   = (const float*)d_in[4];
    const float* W_mid  = (const float*)d_in[5];
    const float* b_mid  = (const float*)d_in[6];
    const float* W_out  = (const float*)d_in[7];
    const float* b_out  = (const float*)d_in[8];
    float* out = (float*)d_out;

    // Replicate Python's RESOLUTIONS exactly (host libm, double precision).
    double bgrow = exp((log(512.0) - log(16.0)) / 3.0);
    int r[4];
    for (int l = 0; l < 4; l++) r[l] = (int)floor(16.0 * pow(bgrow, (double)l));
    int4 res = make_int4(r[0], r[1], r[2], r[3]);

    static bool attr_done = false;
    if (!attr_done) {
        cudaFuncSetAttribute(fused_kernel, cudaFuncAttributeMaxDynamicSharedMemorySize, SMEM_TOTAL);
        attr_done = true;
    }

    prep_kernel<<<(PREP_TOT + 255) / 256, 256>>>(W_mid, W_in);
    fused_kernel<<<N_RAYS / TILE_M, 256, SMEM_TOTAL>>>(
        x, table1, table2, b_in, b_mid, W_out, b_out, out, res);
}